// round 6
// baseline (speedup 1.0000x reference)
#include <cuda_runtime.h>
#include <cstdint>

typedef unsigned long long u64;

// Fused Tucker linear layer, fp32, f32x2 packed FMA everywhere.
// Grid: 256 CTAs x 256 threads, 16 samples/CTA, 2 CTAs/SM.

#define THREADS 256
#define SPB 16
#define SB  4

// smem float offsets
//  zs  : [512][20]                     10240
//  t1u : ph1 t1 [4][16][132]=8448 ; ph2-end U[16][512]=8192
//  scr : 8256 : x-stage 8192 / t2 4096 / core tile (u64 [8][516]) / s1 2048u64
//  fs  : f5 plain 128 | f3 plain 128 | f4d 256 | f0d 256 | f1d 256 | f2t 256
#define ZS_OFF   0
#define T1_OFF   10240
#define SCR_OFF  (10240 + 8448)
#define FS_OFF   (SCR_OFF + 8256)
#define F5O 0
#define F3O 128
#define F4D 256
#define F0D 512
#define F1D 768
#define F2T 1024
#define SMEM_FLOATS (FS_OFF + 1280)
#define SMEM_BYTES  (SMEM_FLOATS * 4)

__device__ __forceinline__ u64 dup2(float v) {
    u64 r; asm("mov.b64 %0, {%1, %1};" : "=l"(r) : "f"(v)); return r;
}
__device__ __forceinline__ void fma2(u64& acc, u64 a, u64 b) {
    asm("fma.rn.f32x2 %0, %1, %2, %0;" : "+l"(acc) : "l"(a), "l"(b));
}
__device__ __forceinline__ void unpack2(u64 v, float& lo, float& hi) {
    asm("mov.b64 {%0, %1}, %2;" : "=f"(lo), "=f"(hi) : "l"(v));
}

__global__ __launch_bounds__(THREADS, 2) void tucker_fused(
    const float* __restrict__ x, const float* __restrict__ core,
    const float* __restrict__ f0, const float* __restrict__ f1,
    const float* __restrict__ f2, const float* __restrict__ f3,
    const float* __restrict__ f4, const float* __restrict__ f5,
    const float* __restrict__ bias, float* __restrict__ y)
{
    extern __shared__ float sm[];
    float* zs  = sm + ZS_OFF;
    float* t1u = sm + T1_OFF;
    float* scr = sm + SCR_OFF;
    float* fs  = sm + FS_OFF;

    const int tid = threadIdx.x;
    const int s0 = blockIdx.x * SPB;

    if (tid < 128) {
        fs[F5O + tid] = f5[tid];
        fs[F3O + tid] = f3[tid];
        float v4 = f4[tid]; fs[F4D + 2 * tid] = v4; fs[F4D + 2 * tid + 1] = v4;
        float v0 = f0[tid]; fs[F0D + 2 * tid] = v0; fs[F0D + 2 * tid + 1] = v0;
        float v1 = f1[tid]; fs[F1D + 2 * tid] = v1; fs[F1D + 2 * tid + 1] = v1;
    }
    if (tid < 64) {   // f2t[k][cp] = {f2[2cp][k], f2[2cp+1][k]}
        int k = tid >> 3, cp = tid & 7;
        fs[F2T + tid * 2]     = f2[(2 * cp) * 8 + k];
        fs[F2T + tid * 2 + 1] = f2[(2 * cp + 1) * 8 + k];
    }
    __syncthreads();

    // ================= PHASE 1: in-side -> zs[k][s] =================
    {
        for (int sb = 0; sb < SPB; sb += SB) {
#pragma unroll
            for (int pair = 0; pair < SB / 2; pair++) {
                // stage 2 samples (coalesced)
                float4* xs4 = (float4*)scr;
#pragma unroll
                for (int i = 0; i < 8; i++) {
                    int g = i * THREADS + tid;
                    int sl = g >> 10;
                    const float4* xp = (const float4*)(x + ((size_t)(s0 + sb + pair * 2 + sl) << 12));
                    xs4[g] = xp[g & 1023];
                }
                __syncthreads();
                // 1a: t1[sl][d][e*8+nn] = sum_f x[de*16+f] * f5[f][nn]   (nn-pair packed)
#pragma unroll
                for (int it = 0; it < 2; it++) {
                    int r = it * THREADS + tid;         // 0..511 = sl*256 + de
                    int sl2 = r >> 8, de = r & 255;
                    int d = de >> 4, e = de & 15;
                    const float* xb = scr + sl2 * 4096 + de * 16;
                    float xv[16];
                    *(float4*)&xv[0]  = *(const float4*)&xb[0];
                    *(float4*)&xv[4]  = *(const float4*)&xb[4];
                    *(float4*)&xv[8]  = *(const float4*)&xb[8];
                    *(float4*)&xv[12] = *(const float4*)&xb[12];
                    u64 v2[4] = {0ull, 0ull, 0ull, 0ull};
#pragma unroll
                    for (int f = 0; f < 16; f++) {
                        u64 xd = dup2(xv[f]);
#pragma unroll
                        for (int np = 0; np < 4; np++)
                            fma2(v2[np], xd, *(const u64*)&fs[F5O + f * 8 + np * 2]);
                    }
                    int sl = pair * 2 + sl2;
                    u64* ob = (u64*)(t1u + sl * 2112 + d * 132 + e * 8);
                    ob[0] = v2[0]; ob[1] = v2[1]; ob[2] = v2[2]; ob[3] = v2[3];
                }
                __syncthreads();
            }
            // 1b: t2[sl][d][m][nn-pair] = sum_e f4d[e][m] * t1pair[sl][d][e][nn-pair]
            float* t2 = scr;   // [4][16][8][8] = 4096 floats (u64 pairs over nn)
#pragma unroll
            for (int it = 0; it < 8; it++) {
                int p = it * THREADS + tid;              // 0..2047 pair-slots
                int np = p & 3, m = (p >> 2) & 7, d = (p >> 5) & 15, sl = p >> 9;
                const u64* base = (const u64*)(t1u + sl * 2112 + d * 132 + np * 2);
                u64 acc = 0ull;
#pragma unroll
                for (int e = 0; e < 8; e++)
                    fma2(acc, base[e * 4], *(const u64*)&fs[F4D + (e * 8 + m) * 2]);
                u64 acc1 = 0ull;
#pragma unroll
                for (int e = 8; e < 16; e++)
                    fma2(acc1, base[e * 4], *(const u64*)&fs[F4D + (e * 8 + m) * 2]);
                float l0, h0, l1, h1;
                unpack2(acc, l0, h0); unpack2(acc1, l1, h1);
                int idx = sl * 1024 + d * 64 + m * 8 + np * 2;
                t2[idx] = l0 + l1; t2[idx + 1] = h0 + h1;
            }
            __syncthreads();
            // 1c: zs[k][sb+sl] = sum_d f3[d][l] * t2[sl][d][m][nn]
#pragma unroll
            for (int it = 0; it < 8; it++) {
                int idx = it * THREADS + tid;            // 0..2047
                int k = idx & 511, sl = idx >> 9;
                int mn = k & 63, l = k >> 6;
                const float* base = scr + (sl << 10) + mn;
                float a0 = 0.f, a1 = 0.f;
#pragma unroll
                for (int d = 0; d < 16; d += 2) {
                    a0 += fs[F3O + d * 8 + l] * base[d << 6];
                    a1 += fs[F3O + (d + 1) * 8 + l] * base[(d + 1) << 6];
                }
                zs[k * 20 + sb + sl] = a0 + a1;
            }
            __syncthreads();
        }
    }

    // ================= PHASE 2: U[16,512] = Z @ core^T =================
    {
        u64* tile = (u64*)scr;      // [8][516] dup'd core values
        u64 acc2[8][2];
#pragma unroll
        for (int a = 0; a < 8; a++) { acc2[a][0] = 0ull; acc2[a][1] = 0ull; }

        const float4* core4 = (const float4*)core;
        float4 pf[4];
#pragma unroll
        for (int i = 0; i < 4; i++) {
            int g = i * THREADS + tid;
            int o = g >> 1, kh = g & 1;
            pf[i] = core4[o * 128 + kh];
        }

#pragma unroll 1
        for (int kt = 0; kt < 64; kt++) {
            __syncthreads();      // previous chunk fully read
#pragma unroll
            for (int i = 0; i < 4; i++) {
                int g = i * THREADS + tid;
                int o = g >> 1, kh = g & 1;
                const float* c = (const float*)&pf[i];
#pragma unroll
                for (int j = 0; j < 4; j++)
                    tile[(kh * 4 + j) * 516 + o] = dup2(c[j]);
            }
            __syncthreads();      // tile visible
            if (kt < 63) {
#pragma unroll
                for (int i = 0; i < 4; i++) {
                    int g = i * THREADS + tid;
                    int o = g >> 1, kh = g & 1;
                    pf[i] = core4[o * 128 + (kt + 1) * 2 + kh];
                }
            }
#pragma unroll
            for (int k8 = 0; k8 < 8; k8++) {
                const float* ap = zs + (kt * 8 + k8) * 20;
                ulonglong2 q0 = *(const ulonglong2*)ap;         // s0..3
                ulonglong2 q1 = *(const ulonglong2*)(ap + 4);   // s4..7
                ulonglong2 q2 = *(const ulonglong2*)(ap + 8);   // s8..11
                ulonglong2 q3 = *(const ulonglong2*)(ap + 12);  // s12..15
                u64 av[8] = {q0.x, q0.y, q1.x, q1.y, q2.x, q2.y, q3.x, q3.y};
                u64 bA = tile[k8 * 516 + tid];
                u64 bB = tile[k8 * 516 + 256 + tid];
#pragma unroll
                for (int s2 = 0; s2 < 8; s2++) {
                    fma2(acc2[s2][0], av[s2], bA);
                    fma2(acc2[s2][1], av[s2], bB);
                }
            }
        }
        __syncthreads();
        // store U -> t1u region  usb[s][512]
        float* usb = t1u;
#pragma unroll
        for (int s2 = 0; s2 < 8; s2++) {
            float lo, hi;
            unpack2(acc2[s2][0], lo, hi);
            usb[(2 * s2) * 512 + tid] = lo;
            usb[(2 * s2 + 1) * 512 + tid] = hi;
            unpack2(acc2[s2][1], lo, hi);
            usb[(2 * s2) * 512 + 256 + tid] = lo;
            usb[(2 * s2 + 1) * 512 + 256 + tid] = hi;
        }
        __syncthreads();
    }

    // ================= PHASE 3: out-side + bias -> y =================
    {
        float* usb = t1u;
        u64* s1u = (u64*)scr;       // [4sl][16a][32 jk-pairs] = 2048 u64

        for (int sb = 0; sb < SPB; sb += SB) {
            // s1[sl][a][jk-pair] = sum_i f0d[a][i] * u-pair
#pragma unroll
            for (int it = 0; it < 8; it++) {
                int p = it * THREADS + tid;          // 0..2047
                int q = p & 31, a = (p >> 5) & 15, sl = p >> 9;
                const u64* ub = (const u64*)(usb + (sb + sl) * 512 + 2 * q);
                u64 acc = 0ull;
#pragma unroll
                for (int i = 0; i < 8; i++)
                    fma2(acc, ub[i * 32], *(const u64*)&fs[F0D + (a * 8 + i) * 2]);
                s1u[p] = acc;
            }
            __syncthreads();
            // y[s][a*256+b*16+c] with c-pairs packed
#pragma unroll
            for (int it = 0; it < 4; it++) {
                int r = it * THREADS + tid;          // 0..1023 = sl*256 + a*16 + b
                int b = r & 15, a = (r >> 4) & 15, sl = r >> 8;
                const u64* sp = s1u + (sl * 16 + a) * 32;
                // w pairs over k
                u64 wp[4];
#pragma unroll
                for (int kp = 0; kp < 4; kp++) {
                    u64 acc = 0ull;
#pragma unroll
                    for (int j = 0; j < 8; j++)
                        fma2(acc, sp[j * 4 + kp], *(const u64*)&fs[F1D + (b * 8 + j) * 2]);
                    wp[kp] = acc;
                }
                float w[8];
#pragma unroll
                for (int kp = 0; kp < 4; kp++) unpack2(wp[kp], w[2 * kp], w[2 * kp + 1]);
                u64 wd[8];
#pragma unroll
                for (int k = 0; k < 8; k++) wd[k] = dup2(w[k]);

                const u64* bp = (const u64*)(bias + a * 256 + b * 16);
                u64 op[8];
#pragma unroll
                for (int cp = 0; cp < 8; cp++) {
                    u64 acc = __ldg(bp + cp);
#pragma unroll
                    for (int k = 0; k < 8; k++)
                        fma2(acc, wd[k], *(const u64*)&fs[F2T + (k * 8 + cp) * 2]);
                    op[cp] = acc;
                }
                u64* yo = (u64*)(y + ((size_t)(s0 + sb + sl) << 12) + a * 256 + b * 16);
#pragma unroll
                for (int c2 = 0; c2 < 4; c2++) {
                    ulonglong2 v; v.x = op[2 * c2]; v.y = op[2 * c2 + 1];
                    *(ulonglong2*)(yo + 2 * c2) = v;
                }
            }
            __syncthreads();
        }
    }
}

extern "C" void kernel_launch(void* const* d_in, const int* in_sizes, int n_in,
                              void* d_out, int out_size) {
    const float* x    = (const float*)d_in[0];
    const float* core = (const float*)d_in[1];
    const float* f0   = (const float*)d_in[2];
    const float* f1   = (const float*)d_in[3];
    const float* f2   = (const float*)d_in[4];
    const float* f3   = (const float*)d_in[5];
    const float* f4   = (const float*)d_in[6];
    const float* f5   = (const float*)d_in[7];
    const float* bias = (const float*)d_in[8];
    float* y = (float*)d_out;

    cudaFuncSetAttribute(tucker_fused, cudaFuncAttributeMaxDynamicSharedMemorySize, SMEM_BYTES);
    tucker_fused<<<256, THREADS, SMEM_BYTES>>>(x, core, f0, f1, f2, f3, f4, f5, bias, y);
}

// round 9
// speedup vs baseline: 1.6299x; 1.6299x over previous
#include <cuda_runtime.h>
#include <cstdint>

// Fused Tucker linear layer, fp32 scalar FMA, conflict-free smem layouts.
// Grid: 256 CTAs x 256 threads, 16 samples/CTA, 2 CTAs/SM.

#define THREADS 256
#define SPB 16
#define SB  4

// smem float offsets
//  zs  : [512][20]  z transposed [k][s]         -> 10240
//  usb : 8192  : ph1 t1 [4][2048] ; ph2 output U[16][512] ; ph3 input
//  scr : 8256  : ph1 x-stage 8192 / t2 4096 ; ph2 core tile [16][516] ; ph3 s1 4096
//  fs  : 768   : f0|f1|f2|f3|f4|f5 (128 each)
#define ZS_OFF   0
#define US_OFF   10240
#define SCR_OFF  (10240 + 8192)
#define FS_OFF   (SCR_OFF + 8256)
#define SMEM_FLOATS (FS_OFF + 768)
#define SMEM_BYTES  (SMEM_FLOATS * 4)

__global__ __launch_bounds__(THREADS, 2) void tucker_fused(
    const float* __restrict__ x, const float* __restrict__ core,
    const float* __restrict__ f0, const float* __restrict__ f1,
    const float* __restrict__ f2, const float* __restrict__ f3,
    const float* __restrict__ f4, const float* __restrict__ f5,
    const float* __restrict__ bias, float* __restrict__ y)
{
    extern __shared__ float sm[];
    float* zs  = sm + ZS_OFF;
    float* usb = sm + US_OFF;
    float* scr = sm + SCR_OFF;
    float* fs  = sm + FS_OFF;

    const int tid = threadIdx.x;
    const int s0 = blockIdx.x * SPB;

    if (tid < 128) {
        fs[tid]       = f0[tid];
        fs[128 + tid] = f1[tid];
        fs[256 + tid] = f2[tid];
        fs[384 + tid] = f3[tid];
        fs[512 + tid] = f4[tid];
        fs[640 + tid] = f5[tid];
    }
    __syncthreads();

    // ================= PHASE 1: in-side -> zs[k][s] =================
    {
        const float* f3s = fs + 384;
        const float* f4s = fs + 512;
        const float* f5s = fs + 640;
        float* t1 = usb;   // [SB][256][8] = 8192

        for (int sb = 0; sb < SPB; sb += SB) {
#pragma unroll
            for (int pair = 0; pair < SB / 2; pair++) {
                // stage 2 samples (coalesced)
                float4* xs4 = (float4*)scr;
#pragma unroll
                for (int i = 0; i < 8; i++) {
                    int g = i * THREADS + tid;
                    int sl = g >> 10;
                    const float4* xp = (const float4*)(x + ((size_t)(s0 + sb + pair * 2 + sl) << 12));
                    xs4[g] = xp[g & 1023];
                }
                __syncthreads();
                // 1a: t1[sl][de][nn] = sum_f x[de*16+f] * f5[f][nn]
#pragma unroll 2
                for (int it = 0; it < 16; it++) {
                    int idx = it * THREADS + tid;        // 0..4095
                    int nn = idx & 7, de = (idx >> 3) & 255, sl = idx >> 11;
                    const float* xb = scr + sl * 4096 + de * 16;
                    float a0 = 0.f, a1 = 0.f;
#pragma unroll
                    for (int f = 0; f < 16; f += 2) {
                        a0 += xb[f] * f5s[f * 8 + nn];
                        a1 += xb[f + 1] * f5s[(f + 1) * 8 + nn];
                    }
                    t1[((pair * 2 + sl) << 11) + (idx & 2047)] = a0 + a1;
                }
                __syncthreads();
            }
            // 1b: t2[sl][d][m][nn] = sum_e f4[e][m] * t1[sl][d*16+e][nn]
            float* t2 = scr;   // [4][16][8][8] = 4096
#pragma unroll 4
            for (int it = 0; it < 16; it++) {
                int idx = it * THREADS + tid;            // 0..4095
                int nn = idx & 7, m = (idx >> 3) & 7, d = (idx >> 6) & 15, sl = idx >> 10;
                const float* base = t1 + (((sl << 4) + d) << 7) + nn;
                float a0 = 0.f, a1 = 0.f;
#pragma unroll
                for (int e = 0; e < 16; e += 2) {
                    a0 += f4s[e * 8 + m] * base[e * 8];
                    a1 += f4s[(e + 1) * 8 + m] * base[(e + 1) * 8];
                }
                t2[idx] = a0 + a1;
            }
            __syncthreads();
            // 1c: zs[k][sb+sl] = sum_d f3[d][l] * t2[sl][d][m][nn],  k = l*64+m*8+nn
#pragma unroll 4
            for (int it = 0; it < 8; it++) {
                int idx = it * THREADS + tid;            // 0..2047
                int k = idx & 511, sl = idx >> 9;
                int mn = k & 63, l = k >> 6;
                const float* base = scr + (sl << 10) + mn;
                float a0 = 0.f, a1 = 0.f;
#pragma unroll
                for (int d = 0; d < 16; d += 2) {
                    a0 += fs[384 + d * 8 + l] * base[d << 6];
                    a1 += fs[384 + (d + 1) * 8 + l] * base[(d + 1) << 6];
                }
                zs[k * 20 + sb + sl] = a0 + a1;
            }
            __syncthreads();
        }
    }

    // ================= PHASE 2: U[16,512] = Z @ core^T (scalar, conflict-free) =====
    // tile[16][516]: element (kk, o) at kk*516 + (o ^ ((kk>>2)*8))
    {
        float* tile = scr;
        const int sg = tid >> 7;          // 0..1 -> 8-sample half
        const int og = tid & 127;         // 0..127 -> 4-o block
        const int o0 = tid >> 2;          // store: o base (0..63), o = o0 + i*64
        const int kq = tid & 3;           // store: k quad
        const int sbase = kq * 2064 + (o0 ^ (kq * 8));
        int lb[4];
        lb[0] = og * 4;
        lb[1] = (og * 4) ^ 8;
        lb[2] = (og * 4) ^ 16;
        lb[3] = (og * 4) ^ 24;

        float acc[8][4];
#pragma unroll
        for (int s = 0; s < 8; s++)
#pragma unroll
            for (int o = 0; o < 4; o++) acc[s][o] = 0.f;

        const float4* core4 = (const float4*)core;
        float4 pf[8];
#pragma unroll
        for (int i = 0; i < 8; i++)
            pf[i] = core4[(o0 + i * 64) * 128 + kq];

#pragma unroll 1
        for (int kt = 0; kt < 32; kt++) {
            __syncthreads();          // previous tile fully consumed
#pragma unroll
            for (int i = 0; i < 8; i++) {
                float* sp = tile + sbase + i * 64;
                sp[0]    = pf[i].x;
                sp[516]  = pf[i].y;
                sp[1032] = pf[i].z;
                sp[1548] = pf[i].w;
            }
            __syncthreads();          // tile visible
            if (kt < 31) {
#pragma unroll
                for (int i = 0; i < 8; i++)
                    pf[i] = core4[(o0 + i * 64) * 128 + (kt + 1) * 4 + kq];
            }
#pragma unroll
            for (int kk = 0; kk < 16; kk++) {
                const float* ar = zs + (kt * 16 + kk) * 20 + sg * 8;
                float a[8];
                *(float4*)&a[0] = *(const float4*)ar;        // broadcast
                *(float4*)&a[4] = *(const float4*)(ar + 4);  // broadcast
                float b[4];
                *(float4*)b = *(const float4*)&tile[kk * 516 + lb[kk >> 2]];
#pragma unroll
                for (int s = 0; s < 8; s++)
#pragma unroll
                    for (int o = 0; o < 4; o++) acc[s][o] += a[s] * b[o];
            }
        }
        __syncthreads();
        // store U -> usb[s][512]
#pragma unroll
        for (int s = 0; s < 8; s++)
            *(float4*)&usb[(sg * 8 + s) * 512 + og * 4] = *(float4*)acc[s];
        __syncthreads();
    }

    // ================= PHASE 3: out-side + bias -> y =================
    {
        const float* f0s = fs;
        const float* f1s = fs + 128;
        const float* f2s = fs + 256;
        float* s1 = scr;   // [SB][16][8][8] = 4096

        for (int sb = 0; sb < SPB; sb += SB) {
            // s1[sl][a][j][k] = sum_i f0[a][i] * u[s][i*64 + j*8 + k]
#pragma unroll 4
            for (int it = 0; it < 16; it++) {
                int idx = it * THREADS + tid;            // 0..4095
                int jk = idx & 63, a = (idx >> 6) & 15, sl = idx >> 10;
                const float* ub = usb + (sb + sl) * 512 + jk;
                float a0 = 0.f, a1 = 0.f;
#pragma unroll
                for (int i = 0; i < 8; i += 2) {
                    a0 += f0s[a * 8 + i] * ub[i * 64];
                    a1 += f0s[a * 8 + i + 1] * ub[(i + 1) * 64];
                }
                s1[idx] = a0 + a1;
            }
            __syncthreads();
            // y = sum_k f2[c][k] * (sum_j f1[b][j] * s1[sl][a][j][k]) + bias
#pragma unroll
            for (int it = 0; it < 4; it++) {
                int r = it * THREADS + tid;              // 0..1023 = sl*256 + a*16 + b
                int b = r & 15, a = (r >> 4) & 15, sl = r >> 8;
                const float* sp = s1 + ((sl * 16 + a) << 6);
                float w[8];
#pragma unroll
                for (int k = 0; k < 8; k++) {
                    float acc = 0.f;
#pragma unroll
                    for (int j = 0; j < 8; j++) acc += f1s[b * 8 + j] * sp[j * 8 + k];
                    w[k] = acc;
                }
                float* yo = y + ((size_t)(s0 + sb + sl) << 12) + a * 256 + b * 16;
                const float4* bp = (const float4*)(bias + a * 256 + b * 16);
#pragma unroll
                for (int c4 = 0; c4 < 4; c4++) {
                    float4 bv = __ldg(bp + c4);
                    float out[4] = {bv.x, bv.y, bv.z, bv.w};
#pragma unroll
                    for (int ci = 0; ci < 4; ci++) {
                        int c = c4 * 4 + ci;
#pragma unroll
                        for (int k = 0; k < 8; k++) out[ci] += f2s[c * 8 + k] * w[k];
                    }
                    *(float4*)(yo + c4 * 4) = make_float4(out[0], out[1], out[2], out[3]);
                }
            }
            __syncthreads();
        }
    }
}

extern "C" void kernel_launch(void* const* d_in, const int* in_sizes, int n_in,
                              void* d_out, int out_size) {
    const float* x    = (const float*)d_in[0];
    const float* core = (const float*)d_in[1];
    const float* f0   = (const float*)d_in[2];
    const float* f1   = (const float*)d_in[3];
    const float* f2   = (const float*)d_in[4];
    const float* f3   = (const float*)d_in[5];
    const float* f4   = (const float*)d_in[6];
    const float* f5   = (const float*)d_in[7];
    const float* bias = (const float*)d_in[8];
    float* y = (float*)d_out;

    cudaFuncSetAttribute(tucker_fused, cudaFuncAttributeMaxDynamicSharedMemorySize, SMEM_BYTES);
    tucker_fused<<<256, THREADS, SMEM_BYTES>>>(x, core, f0, f1, f2, f3, f4, f5, bias, y);
}